// round 15
// baseline (speedup 1.0000x reference)
#include <cuda_runtime.h>
#include <cuda_fp16.h>
#include <math.h>
#include <stdint.h>

#define NB    4
#define QL    64
#define NH    32
#define HD    128
#define CTX   4096
#define TOT   4160
#define HID   4096
#define EPSR  1e-6f
#define INV_SQRT_D 0.08838834764831843f
#define SPLIT 8

__device__ float g_qraw[NB * QL * HID];
__device__ half  g_q_h [NB * NH * QL * HD];
__device__ half  g_hs_h [NB * QL * HID];
__device__ half  g_attn_h[NB * QL * HID];
__device__ half  g_wq_h[HID * HID];
__device__ half  g_wo_h[HID * HID];
__device__ half  g_kh[(size_t)NB * TOT * HID];   // pre-roped K, fp16
__device__ half  g_vh[(size_t)NB * TOT * HID];   // raw V, fp16
__device__ float g_pO[SPLIT * NB * NH * QL * HD];
__device__ float g_pm[SPLIT * NB * NH * QL];
__device__ float g_pl[SPLIT * NB * NH * QL];

// ---------------------------------------------------------------------------
// helpers
// ---------------------------------------------------------------------------
__device__ __forceinline__ uint32_t smaddr(const void* p) {
    return (uint32_t)__cvta_generic_to_shared(p);
}
__device__ __forceinline__ void ldsm4(uint32_t& r0, uint32_t& r1, uint32_t& r2, uint32_t& r3, uint32_t a) {
    asm volatile("ldmatrix.sync.aligned.m8n8.x4.shared.b16 {%0,%1,%2,%3}, [%4];"
                 : "=r"(r0), "=r"(r1), "=r"(r2), "=r"(r3) : "r"(a));
}
__device__ __forceinline__ void ldsm4t(uint32_t& r0, uint32_t& r1, uint32_t& r2, uint32_t& r3, uint32_t a) {
    asm volatile("ldmatrix.sync.aligned.m8n8.x4.trans.shared.b16 {%0,%1,%2,%3}, [%4];"
                 : "=r"(r0), "=r"(r1), "=r"(r2), "=r"(r3) : "r"(a));
}
__device__ __forceinline__ void mma16816(float d[4],
                                         uint32_t a0, uint32_t a1, uint32_t a2, uint32_t a3,
                                         uint32_t b0, uint32_t b1) {
    asm volatile(
        "mma.sync.aligned.m16n8k16.row.col.f32.f16.f16.f32 "
        "{%0,%1,%2,%3},{%4,%5,%6,%7},{%8,%9},{%0,%1,%2,%3};"
        : "+f"(d[0]), "+f"(d[1]), "+f"(d[2]), "+f"(d[3])
        : "r"(a0), "r"(a1), "r"(a2), "r"(a3), "r"(b0), "r"(b1));
}
__device__ __forceinline__ uint32_t pack2(float x, float y) {
    __half2 h = __floats2half2_rn(x, y);
    return *(uint32_t*)&h;
}
__device__ __forceinline__ void cpa16(uint32_t dst, const void* src) {
    asm volatile("cp.async.cg.shared.global [%0], [%1], 16;" :: "r"(dst), "l"(src));
}
#define CP_COMMIT() asm volatile("cp.async.commit_group;")
#define CP_WAIT(n)  asm volatile("cp.async.wait_group %0;" :: "n"(n))

// ---------------------------------------------------------------------------
// fp32 -> fp16 conversion, 16 elems/thread. cols fixed at 4096.
// ---------------------------------------------------------------------------
__global__ __launch_bounds__(256) void cvt_f2h(const float* __restrict__ src,
                                               half* __restrict__ dst, int ld)
{
    size_t i = ((size_t)blockIdx.x * 256 + threadIdx.x) * 16;
    size_t row = i >> 12;
    int    col = (int)(i & 4095);
    const float* s = src + row * (size_t)ld + col;
    half* d = dst + row * 4096 + col;
    float4 v0 = *(const float4*)(s);
    float4 v1 = *(const float4*)(s + 4);
    float4 v2 = *(const float4*)(s + 8);
    float4 v3 = *(const float4*)(s + 12);
    *(uint2*)(d)      = make_uint2(pack2(v0.x, v0.y), pack2(v0.z, v0.w));
    *(uint2*)(d + 4)  = make_uint2(pack2(v1.x, v1.y), pack2(v1.z, v1.w));
    *(uint2*)(d + 8)  = make_uint2(pack2(v2.x, v2.y), pack2(v2.z, v2.w));
    *(uint2*)(d + 12) = make_uint2(pack2(v3.x, v3.y), pack2(v3.z, v3.w));
}

// ---------------------------------------------------------------------------
// KV prep v2: raw fp32 concat(th, hs) -> pre-roped K (fp16) + raw V (fp16).
// 8 rope pairs per thread: 12 independent LDG.128, 4 STG.128 (high MLP).
// Grid: NB*TOT*2048 pairs / 8 / 256 = 16640 blocks.
// ---------------------------------------------------------------------------
__global__ __launch_bounds__(256) void kv_prep(const float* __restrict__ th,
                                               const float* __restrict__ hs,
                                               const float* __restrict__ cosb,
                                               const float* __restrict__ sinb)
{
    size_t i8 = ((size_t)blockIdx.x * 256 + threadIdx.x) * 8;   // pair base idx
    size_t row = i8 >> 11;               // 2048 pairs per (b,p) row
    int inrow = (int)(i8 & 2047);
    int h  = inrow >> 6;
    int dl = inrow & 63;                 // multiple of 8
    int b = (int)(row / TOT), p = (int)(row % TOT);

    const float* src = ((p < CTX) ? th + ((size_t)b * CTX + p) * HID
                                  : hs + ((size_t)b * QL + (p - CTX)) * HID) + h * HD;
    float4 vl0 = *(const float4*)(src + dl);
    float4 vl1 = *(const float4*)(src + dl + 4);
    float4 vh0 = *(const float4*)(src + dl + 64);
    float4 vh1 = *(const float4*)(src + dl + 68);

    const float* cb = cosb + (size_t)p * HD;
    const float* sb = sinb + (size_t)p * HD;
    float4 cl0 = *(const float4*)(cb + dl),      cl1 = *(const float4*)(cb + dl + 4);
    float4 ch0 = *(const float4*)(cb + dl + 64), ch1 = *(const float4*)(cb + dl + 68);
    float4 sl0 = *(const float4*)(sb + dl),      sl1 = *(const float4*)(sb + dl + 4);
    float4 sh0 = *(const float4*)(sb + dl + 64), sh1 = *(const float4*)(sb + dl + 68);

    size_t dst = ((size_t)b * TOT + p) * HID + (size_t)h * HD;
    *(uint4*)(g_vh + dst + dl) =
        make_uint4(pack2(vl0.x, vl0.y), pack2(vl0.z, vl0.w),
                   pack2(vl1.x, vl1.y), pack2(vl1.z, vl1.w));
    *(uint4*)(g_vh + dst + dl + 64) =
        make_uint4(pack2(vh0.x, vh0.y), pack2(vh0.z, vh0.w),
                   pack2(vh1.x, vh1.y), pack2(vh1.z, vh1.w));

    // K roped: lo = v_lo*c_lo - v_hi*s_lo ; hi = v_hi*c_hi + v_lo*s_hi
    *(uint4*)(g_kh + dst + dl) = make_uint4(
        pack2(vl0.x * cl0.x - vh0.x * sl0.x, vl0.y * cl0.y - vh0.y * sl0.y),
        pack2(vl0.z * cl0.z - vh0.z * sl0.z, vl0.w * cl0.w - vh0.w * sl0.w),
        pack2(vl1.x * cl1.x - vh1.x * sl1.x, vl1.y * cl1.y - vh1.y * sl1.y),
        pack2(vl1.z * cl1.z - vh1.z * sl1.z, vl1.w * cl1.w - vh1.w * sl1.w));
    *(uint4*)(g_kh + dst + dl + 64) = make_uint4(
        pack2(vh0.x * ch0.x + vl0.x * sh0.x, vh0.y * ch0.y + vl0.y * sh0.y),
        pack2(vh0.z * ch0.z + vl0.z * sh0.z, vh0.w * ch0.w + vl0.w * sh0.w),
        pack2(vh1.x * ch1.x + vl1.x * sh1.x, vh1.y * ch1.y + vl1.y * sh1.y),
        pack2(vh1.z * ch1.z + vl1.z * sh1.z, vh1.w * ch1.w + vl1.w * sh1.w));
}

// ---------------------------------------------------------------------------
// fp16 GEMM, BM=32 BN=64 BK=64, 128 threads, 4-stage cp.async, 4 CTAs/SM.
// ---------------------------------------------------------------------------
#define G3_ASLOT 4608
#define G3_BSLOT 9216
#define G3_STAGE (G3_ASLOT + G3_BSLOT)
#define G3_SMEM  (4 * G3_STAGE)

__global__ __launch_bounds__(128, 4) void hgemm3(const half* __restrict__ A,
                                                 const half* __restrict__ B,
                                                 float* __restrict__ C)
{
    extern __shared__ char smc[];
    const uint32_t smBase = smaddr(smc);
    const int tid = threadIdx.x, lane = tid & 31, wid = tid >> 5;
    const int gid = lane >> 2, tig = lane & 3;
    const int wm = wid >> 1, wn = wid & 1;
    const int bx = blockIdx.x, by = blockIdx.y;

    const half* Ab = A + (size_t)(by * 32) * HID;
    const half* Bb = B + (size_t)(bx * 64);

    float acc[4][4];
#pragma unroll
    for (int nt = 0; nt < 4; nt++)
#pragma unroll
        for (int i = 0; i < 4; i++) acc[nt][i] = 0.f;

    const uint32_t aOff = (uint32_t)((wm * 16 + (lane & 15)) * 144 + (lane >> 4) * 16);
    const uint32_t bOff = (uint32_t)(((lane & 7) + 8 * ((lane >> 3) & 1)) * 144
                                     + (wn * 32 + 8 * (lane >> 4)) * 2);

    auto load_stage = [&](int kt) {
        const int slot = kt & 3;
        const int k0 = kt * 64;
        const uint32_t aS = smBase + slot * G3_STAGE;
        const uint32_t bS = aS + G3_ASLOT;
#pragma unroll
        for (int i = 0; i < 2; i++) {
            int u = tid + i * 128, r = u >> 3, c = u & 7;
            cpa16(aS + r * 144 + c * 16, Ab + (size_t)r * HID + k0 + c * 8);
        }
#pragma unroll
        for (int i = 0; i < 4; i++) {
            int u = tid + i * 128, r = u >> 3, c = u & 7;
            cpa16(bS + r * 144 + c * 16, Bb + (size_t)(k0 + r) * HID + c * 8);
        }
        CP_COMMIT();
    };

    load_stage(0); load_stage(1); load_stage(2);

    const int NK = HID / 64;
    for (int kt = 0; kt < NK; kt++) {
        CP_WAIT(2);
        __syncthreads();
        if (kt + 3 < NK) load_stage(kt + 3); else CP_COMMIT();

        const uint32_t aA = smBase + (kt & 3) * G3_STAGE + aOff;
        const uint32_t bA = smBase + (kt & 3) * G3_STAGE + G3_ASLOT + bOff;
#pragma unroll
        for (int kk = 0; kk < 4; kk++) {
            uint32_t x0, x1, x2, x3;
            ldsm4(x0, x1, x2, x3, aA + kk * 32);
#pragma unroll
            for (int nt2 = 0; nt2 < 2; nt2++) {
                uint32_t b0, b1, b2, b3;
                ldsm4t(b0, b1, b2, b3, bA + kk * 16 * 144 + nt2 * 32);
                mma16816(acc[nt2 * 2],     x0, x1, x2, x3, b0, b1);
                mma16816(acc[nt2 * 2 + 1], x0, x1, x2, x3, b2, b3);
            }
        }
    }

    const int row = by * 32 + wm * 16 + gid;
#pragma unroll
    for (int nt = 0; nt < 4; nt++) {
        const int col = bx * 64 + wn * 32 + nt * 8 + 2 * tig;
        *(float2*)(C + (size_t)row * HID + col) =
            make_float2(acc[nt][0], acc[nt][1]);
        *(float2*)(C + (size_t)(row + 8) * HID + col) =
            make_float2(acc[nt][2], acc[nt][3]);
    }
}

// ---------------------------------------------------------------------------
// Q: double RMSNorm + RoPE + fold 1/sqrt(D); writes fp16 directly.
// ---------------------------------------------------------------------------
__global__ __launch_bounds__(256) void qnorm_rope_k(const float* __restrict__ cosb,
                                                    const float* __restrict__ sinb,
                                                    const float* __restrict__ w)
{
    const int gw   = (blockIdx.x * 256 + threadIdx.x) >> 5;
    const int lane = threadIdx.x & 31;
    const int h = gw & 31;
    const int q = (gw >> 5) & 63;
    const int b = gw >> 11;

    const float* src = g_qraw + (size_t)(b * QL + q) * HID + h * HD + lane * 4;
    float4 x4 = *(const float4*)src;
    float  x[4] = {x4.x, x4.y, x4.z, x4.w};
    float4 w4 = *(const float4*)(w + lane * 4);
    float  wv[4] = {w4.x, w4.y, w4.z, w4.w};

    float ss = x[0]*x[0] + x[1]*x[1] + x[2]*x[2] + x[3]*x[3];
#pragma unroll
    for (int o = 16; o > 0; o >>= 1) ss += __shfl_xor_sync(0xffffffffu, ss, o);
    float r1 = rsqrtf(ss * (1.f / 128.f) + EPSR);

    float y[4];
#pragma unroll
    for (int j = 0; j < 4; j++) y[j] = x[j] * r1 * wv[j];

    float ss2 = y[0]*y[0] + y[1]*y[1] + y[2]*y[2] + y[3]*y[3];
#pragma unroll
    for (int o = 16; o > 0; o >>= 1) ss2 += __shfl_xor_sync(0xffffffffu, ss2, o);
    float r2 = rsqrtf(ss2 * (1.f / 128.f) + EPSR);

    float z[4];
#pragma unroll
    for (int j = 0; j < 4; j++) z[j] = y[j] * r2 * wv[j];

    const float4 c4 = *(const float4*)(cosb + (size_t)(CTX + q) * HD + lane * 4);
    const float4 s4 = *(const float4*)(sinb + (size_t)(CTX + q) * HD + lane * 4);
    const float cf[4] = {c4.x, c4.y, c4.z, c4.w};
    const float sf[4] = {s4.x, s4.y, s4.z, s4.w};

    float o_[4];
#pragma unroll
    for (int j = 0; j < 4; j++) {
        float p   = __shfl_xor_sync(0xffffffffu, z[j], 16);
        float rot = (lane < 16) ? -p : p;
        o_[j] = (z[j] * cf[j] + rot * sf[j]) * INV_SQRT_D;
    }
    half* dst = g_q_h + (size_t)((b * NH + h) * QL + q) * HD + lane * 4;
    *(uint2*)dst = make_uint2(pack2(o_[0], o_[1]), pack2(o_[2], o_[3]));
}

// ---------------------------------------------------------------------------
// KV-split flash attention over PRE-CONVERTED fp16 K/V (lean mainloop).
// Grid (128 bh, SPLIT), 256 threads, 2 CTAs/SM, 3-slot cp.async pipeline.
// ---------------------------------------------------------------------------
#define A_SLOT     34816                  // 17408 (Kh) + 17408 (Vh)
#define A_MRED     (3 * A_SLOT)           // 104448
#define ASMEM_BYTES (A_MRED + 1024)

__global__ __launch_bounds__(256, 2) void attn_h()
{
    extern __shared__ char smc[];
    const uint32_t smBase = smaddr(smc);
    float* mred = (float*)(smc + A_MRED);
    float* lred = mred + 128;

    const int bh = blockIdx.x, h = bh & 31, b = bh >> 5;
    const int sp = blockIdx.y;
    const int c0 = (sp == 0) ? 0 : 9 + (sp - 1) * 8;
    const int c1 = (sp == 0) ? 9 : c0 + 8;

    const int tid = threadIdx.x, lane = tid & 31, wid = tid >> 5;
    const int gid = lane >> 2, tig = lane & 3;
    const int wq = wid >> 1, wg = wid & 1;
    const int r0 = wq * 16, j0 = wg * 32;

    const half* khb = g_kh + (size_t)b * TOT * HID + h * HD;
    const half* vhb = g_vh + (size_t)b * TOT * HID + h * HD;

    // Q staging via slot-0 area, then register fragments (before any KV loads)
    {
        half* Qtmp = (half*)smc;
        const half* qsrc = g_q_h + (size_t)bh * (QL * HD);
        for (int e = tid * 4; e < QL * HD; e += 1024) {
            int j = e >> 7, dd = e & 127;
            *(uint2*)&Qtmp[j * 136 + dd] = *(const uint2*)(qsrc + e);
        }
    }
    __syncthreads();
    uint32_t qa[8][4];
    {
        const uint32_t qA = smBase
                          + (uint32_t)((r0 + (lane & 15)) * 272 + (lane >> 4) * 16);
#pragma unroll
        for (int kd = 0; kd < 8; kd++)
            ldsm4(qa[kd][0], qa[kd][1], qa[kd][2], qa[kd][3], qA + kd * 32);
    }
    __syncthreads();   // slot 0 free for KV now

    auto load_chunk = [&](int c) {
        const uint32_t sB = smBase + (c % 3) * A_SLOT;
        const size_t rowb = (size_t)c * 64;
#pragma unroll
        for (int i = 0; i < 8; i++) {
            int u = tid + i * 256;          // 0..2047
            int arr = u >> 10;              // 0: Kh, 1: Vh
            int r = (u >> 4) & 63;
            int cc = u & 15;
            const half* src = (arr ? vhb : khb) + (rowb + r) * HID + cc * 8;
            cpa16(sB + arr * 17408 + r * 272 + cc * 16, src);
        }
        CP_COMMIT();
    };

    load_chunk(c0); load_chunk(c0 + 1); load_chunk(c0 + 2);

    float m_lo = -1e30f, m_hi = -1e30f, l_lo = 0.f, l_hi = 0.f;
    float oacc[16][4];
#pragma unroll
    for (int nt = 0; nt < 16; nt++)
#pragma unroll
        for (int i = 0; i < 4; i++) oacc[nt][i] = 0.f;

    const uint32_t kOff = (uint32_t)((j0 + (lane & 7) + 8 * (lane >> 4)) * 272
                                     + ((lane >> 3) & 1) * 16);
    const uint32_t vOff = (uint32_t)(17408 + (j0 + (lane & 7) + 8 * ((lane >> 3) & 1)) * 272
                                     + (lane >> 4) * 16);

    for (int t = c0; t < c1; t++) {
        CP_WAIT(2);
        __syncthreads();
        const uint32_t sB = smBase + (t % 3) * A_SLOT;
        const uint32_t kA = sB + kOff;
        const uint32_t vA = sB + vOff;

        // QK^T
        float sacc[4][4];
#pragma unroll
        for (int nt = 0; nt < 4; nt++)
#pragma unroll
            for (int i = 0; i < 4; i++) sacc[nt][i] = 0.f;
#pragma unroll
        for (int kd = 0; kd < 8; kd++) {
#pragma unroll
            for (int jt = 0; jt < 2; jt++) {
                uint32_t b0, b1, b2, b3;
                ldsm4(b0, b1, b2, b3, kA + jt * 16 * 272 + kd * 32);
                mma16816(sacc[jt * 2],     qa[kd][0], qa[kd][1], qa[kd][2], qa[kd][3], b0, b1);
                mma16816(sacc[jt * 2 + 1], qa[kd][0], qa[kd][1], qa[kd][2], qa[kd][3], b2, b3);
            }
        }

        // online softmax
        float mx_lo = -1e30f, mx_hi = -1e30f;
#pragma unroll
        for (int nt = 0; nt < 4; nt++) {
            mx_lo = fmaxf(mx_lo, fmaxf(sacc[nt][0], sacc[nt][1]));
            mx_hi = fmaxf(mx_hi, fmaxf(sacc[nt][2], sacc[nt][3]));
        }
        mx_lo = fmaxf(mx_lo, __shfl_xor_sync(0xffffffffu, mx_lo, 1));
        mx_lo = fmaxf(mx_lo, __shfl_xor_sync(0xffffffffu, mx_lo, 2));
        mx_hi = fmaxf(mx_hi, __shfl_xor_sync(0xffffffffu, mx_hi, 1));
        mx_hi = fmaxf(mx_hi, __shfl_xor_sync(0xffffffffu, mx_hi, 2));

        float nm_lo = fmaxf(m_lo, mx_lo), nm_hi = fmaxf(m_hi, mx_hi);
        float al_lo = __expf(m_lo - nm_lo), al_hi = __expf(m_hi - nm_hi);
        float sum_lo = 0.f, sum_hi = 0.f;
        uint32_t pa0[4], pa1[4];
#pragma unroll
        for (int nt = 0; nt < 4; nt++) {
            float e0 = __expf(sacc[nt][0] - nm_lo);
            float e1 = __expf(sacc[nt][1] - nm_lo);
            float e2 = __expf(sacc[nt][2] - nm_hi);
            float e3 = __expf(sacc[nt][3] - nm_hi);
            sum_lo += e0 + e1;  sum_hi += e2 + e3;
            pa0[nt] = pack2(e0, e1);
            pa1[nt] = pack2(e2, e3);
        }
        sum_lo += __shfl_xor_sync(0xffffffffu, sum_lo, 1);
        sum_lo += __shfl_xor_sync(0xffffffffu, sum_lo, 2);
        sum_hi += __shfl_xor_sync(0xffffffffu, sum_hi, 1);
        sum_hi += __shfl_xor_sync(0xffffffffu, sum_hi, 2);
        l_lo = l_lo * al_lo + sum_lo;  l_hi = l_hi * al_hi + sum_hi;
        m_lo = nm_lo;  m_hi = nm_hi;

#pragma unroll
        for (int nt = 0; nt < 16; nt++) {
            oacc[nt][0] *= al_lo; oacc[nt][1] *= al_lo;
            oacc[nt][2] *= al_hi; oacc[nt][3] *= al_hi;
        }

        // PV
#pragma unroll
        for (int kc = 0; kc < 2; kc++) {
            uint32_t a0 = pa0[2 * kc], a1 = pa1[2 * kc];
            uint32_t a2 = pa0[2 * kc + 1], a3 = pa1[2 * kc + 1];
#pragma unroll
            for (int dt = 0; dt < 8; dt++) {
                uint32_t b0, b1, b2, b3;
                ldsm4t(b0, b1, b2, b3, vA + kc * 16 * 272 + dt * 32);
                mma16816(oacc[dt * 2],     a0, a1, a2, a3, b0, b1);
                mma16816(oacc[dt * 2 + 1], a0, a1, a2, a3, b2, b3);
            }
        }
        __syncthreads();   // all warps done with slot t before refilling it
        if (t + 3 < c1) load_chunk(t + 3); else CP_COMMIT();
    }

    CP_WAIT(0);
    // in-CTA merge of the 2 key stripes -> partial (unnormalized O, m, l)
    const int rlo = r0 + gid, rhi = r0 + gid + 8;
    if (tig == 0) {
        mred[wg * 64 + rlo] = m_lo;  mred[wg * 64 + rhi] = m_hi;
        lred[wg * 64 + rlo] = l_lo;  lred[wg * 64 + rhi] = l_hi;
    }
    __syncthreads();
    float M_lo = fmaxf(mred[rlo], mred[64 + rlo]);
    float M_hi = fmaxf(mred[rhi], mred[64 + rhi]);
    float L_lo = lred[rlo] * __expf(mred[rlo] - M_lo)
               + lred[64 + rlo] * __expf(mred[64 + rlo] - M_lo);
    float L_hi = lred[rhi] * __expf(mred[rhi] - M_hi)
               + lred[64 + rhi] * __expf(mred[64 + rhi] - M_hi);
    float sc_lo = __expf(m_lo - M_lo);
    float sc_hi = __expf(m_hi - M_hi);
#pragma unroll
    for (int nt = 0; nt < 16; nt++) {
        oacc[nt][0] *= sc_lo; oacc[nt][1] *= sc_lo;
        oacc[nt][2] *= sc_hi; oacc[nt][3] *= sc_hi;
    }

    const size_t pbase = ((size_t)sp * NB * NH + bh) * QL;
    if (tig == 0 && wg == 0) {
        g_pm[pbase + rlo] = M_lo;  g_pm[pbase + rhi] = M_hi;
        g_pl[pbase + rlo] = L_lo;  g_pl[pbase + rhi] = L_hi;
    }

    float* OsmF = (float*)smc;   // overlay (KV slots dead)
    if (wg == 0) {
#pragma unroll
        for (int nt = 0; nt < 16; nt++) {
            const int col = nt * 8 + 2 * tig;
            *(float2*)&OsmF[rlo * 128 + col] = make_float2(oacc[nt][0], oacc[nt][1]);
            *(float2*)&OsmF[rhi * 128 + col] = make_float2(oacc[nt][2], oacc[nt][3]);
        }
    }
    __syncthreads();
    if (wg == 1) {
#pragma unroll
        for (int nt = 0; nt < 16; nt++) {
            const int col = nt * 8 + 2 * tig;
            float2 v0 = *(float2*)&OsmF[rlo * 128 + col];
            float2 v1 = *(float2*)&OsmF[rhi * 128 + col];
            *(float2*)&OsmF[rlo * 128 + col] = make_float2(oacc[nt][0] + v0.x, oacc[nt][1] + v0.y);
            *(float2*)&OsmF[rhi * 128 + col] = make_float2(oacc[nt][2] + v1.x, oacc[nt][3] + v1.y);
        }
    }
    __syncthreads();

    float* pO = g_pO + pbase * HD;
    for (int e = tid * 4; e < QL * HD; e += 1024)
        *(float4*)(pO + e) = *(const float4*)&OsmF[e];
}

// ---------------------------------------------------------------------------
// merge the splits -> fp16 attention output
// ---------------------------------------------------------------------------
__global__ __launch_bounds__(256) void merge_k()
{
    __shared__ float sc[SPLIT][64];
    const int bh = blockIdx.x, h = bh & 31, b = bh >> 5;
    const int tid = threadIdx.x;

    if (tid < 64) {
        float m[SPLIT], l[SPLIT];
#pragma unroll
        for (int s = 0; s < SPLIT; s++) {
            size_t pb = ((size_t)s * NB * NH + bh) * QL + tid;
            m[s] = g_pm[pb];  l[s] = g_pl[pb];
        }
        float M = m[0];
#pragma unroll
        for (int s = 1; s < SPLIT; s++) M = fmaxf(M, m[s]);
        float L = 0.f;
#pragma unroll
        for (int s = 0; s < SPLIT; s++) L += l[s] * __expf(m[s] - M);
        float invL = 1.f / L;
#pragma unroll
        for (int s = 0; s < SPLIT; s++) sc[s][tid] = __expf(m[s] - M) * invL;
    }
    __syncthreads();

    for (int e = tid * 4; e < QL * HD; e += 1024) {
        int row = e >> 7, dd = e & 127;
        float4 acc = make_float4(0.f, 0.f, 0.f, 0.f);
#pragma unroll
        for (int s = 0; s < SPLIT; s++) {
            const float* pO = g_pO + (((size_t)s * NB * NH + bh) * QL) * HD + e;
            float4 v = *(const float4*)pO;
            float f = sc[s][row];
            acc.x += f * v.x; acc.y += f * v.y; acc.z += f * v.z; acc.w += f * v.w;
        }
        *(uint2*)(g_attn_h + (size_t)(b * QL + row) * HID + h * HD + dd) =
            make_uint2(pack2(acc.x, acc.y), pack2(acc.z, acc.w));
    }
}

// ---------------------------------------------------------------------------
extern "C" void kernel_launch(void* const* d_in, const int* in_sizes, int n_in,
                              void* d_out, int out_size)
{
    const float* hs   = (const float*)d_in[0];
    const float* th   = (const float*)d_in[1];
    const float* cosb = (const float*)d_in[2];
    const float* sinb = (const float*)d_in[3];
    const float* Wqkv = (const float*)d_in[4];
    const float* Wo   = (const float*)d_in[5];
    const float* qw   = (const float*)d_in[6];
    float* out = (float*)d_out;

    float *qraw_p;
    half *hs_h, *attn_h_p, *wq_h, *wo_h;
    cudaGetSymbolAddress((void**)&qraw_p, g_qraw);
    cudaGetSymbolAddress((void**)&hs_h,   g_hs_h);
    cudaGetSymbolAddress((void**)&attn_h_p, g_attn_h);
    cudaGetSymbolAddress((void**)&wq_h,   g_wq_h);
    cudaGetSymbolAddress((void**)&wo_h,   g_wo_h);

    cudaFuncSetAttribute(hgemm3, cudaFuncAttributeMaxDynamicSharedMemorySize, G3_SMEM);
    cudaFuncSetAttribute(attn_h, cudaFuncAttributeMaxDynamicSharedMemorySize, ASMEM_BYTES);

    static cudaStream_t s1 = nullptr;
    static cudaEvent_t evRoot = nullptr, evQ = nullptr, evWO = nullptr;
    if (!s1) {
        cudaStreamCreateWithFlags(&s1, cudaStreamNonBlocking);
        cudaEventCreateWithFlags(&evRoot, cudaEventDisableTiming);
        cudaEventCreateWithFlags(&evQ,    cudaEventDisableTiming);
        cudaEventCreateWithFlags(&evWO,   cudaEventDisableTiming);
    }

    cudaEventRecord(evRoot, 0);

    dim3 gg(64, 8);
    // main stream: KV prep starts immediately (the long pole of the front)
    kv_prep<<<16640, 256>>>(th, hs, cosb, sinb);                    // #1

    // side stream: the whole Q chain hides inside kv_prep
    cudaStreamWaitEvent(s1, evRoot, 0);
    cvt_f2h<<<256,  256, 0, s1>>>(hs,   hs_h, HID);                 // #2
    cvt_f2h<<<4096, 256, 0, s1>>>(Wqkv, wq_h, 3 * HID);             // #3
    hgemm3<<<gg, 128, G3_SMEM, s1>>>(hs_h, wq_h, qraw_p);           // #4
    qnorm_rope_k<<<1024, 256, 0, s1>>>(cosb, sinb, qw);             // #5
    cudaEventRecord(evQ, s1);
    cvt_f2h<<<4096, 256, 0, s1>>>(Wo, wo_h, HID);                   // (side tail)
    cudaEventRecord(evWO, s1);

    // main stream: attention after kv_prep (program order) + Q chain (event)
    cudaStreamWaitEvent((cudaStream_t)0, evQ, 0);
    attn_h<<<dim3(NB * NH, SPLIT), 256, ASMEM_BYTES>>>();           // #6 (profiled)
    merge_k<<<NB * NH, 256>>>();                                    // #7

    cudaStreamWaitEvent((cudaStream_t)0, evWO, 0);
    hgemm3<<<gg, 128, G3_SMEM>>>(attn_h_p, wo_h, out);              // #8
}

// round 16
// speedup vs baseline: 1.0362x; 1.0362x over previous
#include <cuda_runtime.h>
#include <cuda_fp16.h>
#include <math.h>
#include <stdint.h>

#define NB    4
#define QL    64
#define NH    32
#define HD    128
#define CTX   4096
#define TOT   4160
#define HID   4096
#define EPSR  1e-6f
#define INV_SQRT_D 0.08838834764831843f
#define SPLIT 8

__device__ float g_qraw[NB * QL * HID];
__device__ half  g_q_h [NB * NH * QL * HD];
__device__ half  g_hs_h [NB * QL * HID];
__device__ half  g_attn_h[NB * QL * HID];
__device__ uint4 g_cs2[TOT * 32];
__device__ float g_pO[SPLIT * NB * NH * QL * HD];
__device__ float g_pm[SPLIT * NB * NH * QL];
__device__ float g_pl[SPLIT * NB * NH * QL];

// ---------------------------------------------------------------------------
// helpers
// ---------------------------------------------------------------------------
__device__ __forceinline__ uint32_t smaddr(const void* p) {
    return (uint32_t)__cvta_generic_to_shared(p);
}
__device__ __forceinline__ void ldsm4(uint32_t& r0, uint32_t& r1, uint32_t& r2, uint32_t& r3, uint32_t a) {
    asm volatile("ldmatrix.sync.aligned.m8n8.x4.shared.b16 {%0,%1,%2,%3}, [%4];"
                 : "=r"(r0), "=r"(r1), "=r"(r2), "=r"(r3) : "r"(a));
}
__device__ __forceinline__ void ldsm4t(uint32_t& r0, uint32_t& r1, uint32_t& r2, uint32_t& r3, uint32_t a) {
    asm volatile("ldmatrix.sync.aligned.m8n8.x4.trans.shared.b16 {%0,%1,%2,%3}, [%4];"
                 : "=r"(r0), "=r"(r1), "=r"(r2), "=r"(r3) : "r"(a));
}
__device__ __forceinline__ void mma16816(float d[4],
                                         uint32_t a0, uint32_t a1, uint32_t a2, uint32_t a3,
                                         uint32_t b0, uint32_t b1) {
    asm volatile(
        "mma.sync.aligned.m16n8k16.row.col.f32.f16.f16.f32 "
        "{%0,%1,%2,%3},{%4,%5,%6,%7},{%8,%9},{%0,%1,%2,%3};"
        : "+f"(d[0]), "+f"(d[1]), "+f"(d[2]), "+f"(d[3])
        : "r"(a0), "r"(a1), "r"(a2), "r"(a3), "r"(b0), "r"(b1));
}
__device__ __forceinline__ uint32_t pack2(float x, float y) {
    __half2 h = __floats2half2_rn(x, y);
    return *(uint32_t*)&h;
}
__device__ __forceinline__ uint32_t hfma2u(uint32_t a, uint32_t b, uint32_t c) {
    __half2 r = __hfma2(*(__half2*)&a, *(__half2*)&b, *(__half2*)&c);
    return *(uint32_t*)&r;
}
__device__ __forceinline__ uint32_t hmul2u(uint32_t a, uint32_t b) {
    __half2 r = __hmul2(*(__half2*)&a, *(__half2*)&b);
    return *(uint32_t*)&r;
}
__device__ __forceinline__ void cpa16(uint32_t dst, const void* src) {
    asm volatile("cp.async.cg.shared.global [%0], [%1], 16;" :: "r"(dst), "l"(src));
}
#define CP_COMMIT() asm volatile("cp.async.commit_group;")
#define CP_WAIT(n)  asm volatile("cp.async.wait_group %0;" :: "n"(n))

// ---------------------------------------------------------------------------
// fp32 -> fp16 conversion, 16 elems/thread. cols fixed at 4096. (hs only)
// ---------------------------------------------------------------------------
__global__ __launch_bounds__(256) void cvt_f2h(const float* __restrict__ src,
                                               half* __restrict__ dst, int ld)
{
    size_t i = ((size_t)blockIdx.x * 256 + threadIdx.x) * 16;
    size_t row = i >> 12;
    int    col = (int)(i & 4095);
    const float* s = src + row * (size_t)ld + col;
    half* d = dst + row * 4096 + col;
    float4 v0 = *(const float4*)(s);
    float4 v1 = *(const float4*)(s + 4);
    float4 v2 = *(const float4*)(s + 8);
    float4 v3 = *(const float4*)(s + 12);
    *(uint2*)(d)      = make_uint2(pack2(v0.x, v0.y), pack2(v0.z, v0.w));
    *(uint2*)(d + 4)  = make_uint2(pack2(v1.x, v1.y), pack2(v1.z, v1.w));
    *(uint2*)(d + 8)  = make_uint2(pack2(v2.x, v2.y), pack2(v2.z, v2.w));
    *(uint2*)(d + 12) = make_uint2(pack2(v3.x, v3.y), pack2(v3.z, v3.w));
}

// sign-folded packed (c, +/-s) table
__global__ __launch_bounds__(256) void cs2_prep(const float* __restrict__ cosb,
                                                const float* __restrict__ sinb)
{
    int i = blockIdx.x * 256 + threadIdx.x;
    if (i >= TOT * 32) return;
    int g    = i & 15;
    int half_ = (i >> 4) & 1;
    int p    = i >> 5;
    int d0   = half_ * 64 + g * 4;
    float4 c = *(const float4*)(cosb + (size_t)p * HD + d0);
    float4 s = *(const float4*)(sinb + (size_t)p * HD + d0);
    float sgn = half_ ? 1.f : -1.f;
    uint4 out;
    out.x = pack2(c.x, c.y);
    out.y = pack2(c.z, c.w);
    out.z = pack2(sgn * s.x, sgn * s.y);
    out.w = pack2(sgn * s.z, sgn * s.w);
    g_cs2[i] = out;
}

// ---------------------------------------------------------------------------
// hgemm4: fp16 A x fp32 B (converted to fp16 in the load path).
// BM=32 BN=64 BK=64, 128 threads, A: 4-stage cp.async, B: 2-slot reg-staged.
// Grid (64, 8). smem 36 KB -> 4 CTAs/SM.
// ---------------------------------------------------------------------------
#define G4_ASLOT 4608                     // 32 * 144
#define G4_BSLOT 9216                     // 64 * 144
#define G4_BBASE (4 * G4_ASLOT)           // 18432
#define G4_SMEM  (G4_BBASE + 2 * G4_BSLOT) // 36864

__global__ __launch_bounds__(128, 4) void hgemm4(const half* __restrict__ A,
                                                 const float* __restrict__ Bf,
                                                 int ldb,
                                                 float* __restrict__ C)
{
    extern __shared__ char smc[];
    const uint32_t smBase = smaddr(smc);
    const int tid = threadIdx.x, lane = tid & 31, wid = tid >> 5;
    const int gid = lane >> 2, tig = lane & 3;
    const int wm = wid >> 1, wn = wid & 1;
    const int bx = blockIdx.x, by = blockIdx.y;

    const half*  Ab = A  + (size_t)(by * 32) * HID;
    const float* Bb = Bf + (size_t)(bx * 64);

    float acc[4][4];
#pragma unroll
    for (int nt = 0; nt < 4; nt++)
#pragma unroll
        for (int i = 0; i < 4; i++) acc[nt][i] = 0.f;

    const uint32_t aOff = (uint32_t)((wm * 16 + (lane & 15)) * 144 + (lane >> 4) * 16);
    const uint32_t bOff = (uint32_t)(((lane & 7) + 8 * ((lane >> 3) & 1)) * 144
                                     + (wn * 32 + 8 * (lane >> 4)) * 2);

    auto loadA = [&](int kt) {
        const int slot = kt & 3;
        const int k0 = kt * 64;
        const uint32_t aS = smBase + slot * G4_ASLOT;
#pragma unroll
        for (int i = 0; i < 2; i++) {
            int u = tid + i * 128, r = u >> 3, c = u & 7;
            cpa16(aS + r * 144 + c * 16, Ab + (size_t)r * HID + k0 + c * 8);
        }
        CP_COMMIT();
    };

    uint4 Breg[4];
    auto ldB = [&](int kt) {
        const int k0 = kt * 64;
#pragma unroll
        for (int i = 0; i < 4; i++) {
            int u = tid + i * 128, r = u >> 3, c = u & 7;
            const float* p = Bb + (size_t)(k0 + r) * ldb + c * 8;
            float4 x = *(const float4*)p;
            float4 y = *(const float4*)(p + 4);
            Breg[i] = make_uint4(pack2(x.x, x.y), pack2(x.z, x.w),
                                 pack2(y.x, y.y), pack2(y.z, y.w));
        }
    };
    auto stB = [&](int kt) {
        char* bS = smc + G4_BBASE + (kt & 1) * G4_BSLOT;
#pragma unroll
        for (int i = 0; i < 4; i++) {
            int u = tid + i * 128, r = u >> 3, c = u & 7;
            *(uint4*)(bS + r * 144 + c * 16) = Breg[i];
        }
    };

    ldB(0);
    loadA(0); loadA(1); loadA(2);

    const int NK = HID / 64;
    for (int kt = 0; kt < NK; kt++) {
        stB(kt);
        CP_WAIT(2);
        __syncthreads();
        if (kt + 1 < NK) ldB(kt + 1);
        if (kt + 3 < NK) loadA(kt + 3); else CP_COMMIT();

        const uint32_t aA = smBase + (kt & 3) * G4_ASLOT + aOff;
        const uint32_t bA = smBase + G4_BBASE + (kt & 1) * G4_BSLOT + bOff;
#pragma unroll
        for (int kk = 0; kk < 4; kk++) {
            uint32_t x0, x1, x2, x3;
            ldsm4(x0, x1, x2, x3, aA + kk * 32);
#pragma unroll
            for (int nt2 = 0; nt2 < 2; nt2++) {
                uint32_t b0, b1, b2, b3;
                ldsm4t(b0, b1, b2, b3, bA + kk * 16 * 144 + nt2 * 32);
                mma16816(acc[nt2 * 2],     x0, x1, x2, x3, b0, b1);
                mma16816(acc[nt2 * 2 + 1], x0, x1, x2, x3, b2, b3);
            }
        }
    }

    const int row = by * 32 + wm * 16 + gid;
#pragma unroll
    for (int nt = 0; nt < 4; nt++) {
        const int col = bx * 64 + wn * 32 + nt * 8 + 2 * tig;
        *(float2*)(C + (size_t)row * HID + col) =
            make_float2(acc[nt][0], acc[nt][1]);
        *(float2*)(C + (size_t)(row + 8) * HID + col) =
            make_float2(acc[nt][2], acc[nt][3]);
    }
}

// ---------------------------------------------------------------------------
// Q: double RMSNorm + RoPE + fold 1/sqrt(D); writes fp16 directly.
// ---------------------------------------------------------------------------
__global__ __launch_bounds__(256) void qnorm_rope_k(const float* __restrict__ cosb,
                                                    const float* __restrict__ sinb,
                                                    const float* __restrict__ w)
{
    const int gw   = (blockIdx.x * 256 + threadIdx.x) >> 5;
    const int lane = threadIdx.x & 31;
    const int h = gw & 31;
    const int q = (gw >> 5) & 63;
    const int b = gw >> 11;

    const float* src = g_qraw + (size_t)(b * QL + q) * HID + h * HD + lane * 4;
    float4 x4 = *(const float4*)src;
    float  x[4] = {x4.x, x4.y, x4.z, x4.w};
    float4 w4 = *(const float4*)(w + lane * 4);
    float  wv[4] = {w4.x, w4.y, w4.z, w4.w};

    float ss = x[0]*x[0] + x[1]*x[1] + x[2]*x[2] + x[3]*x[3];
#pragma unroll
    for (int o = 16; o > 0; o >>= 1) ss += __shfl_xor_sync(0xffffffffu, ss, o);
    float r1 = rsqrtf(ss * (1.f / 128.f) + EPSR);

    float y[4];
#pragma unroll
    for (int j = 0; j < 4; j++) y[j] = x[j] * r1 * wv[j];

    float ss2 = y[0]*y[0] + y[1]*y[1] + y[2]*y[2] + y[3]*y[3];
#pragma unroll
    for (int o = 16; o > 0; o >>= 1) ss2 += __shfl_xor_sync(0xffffffffu, ss2, o);
    float r2 = rsqrtf(ss2 * (1.f / 128.f) + EPSR);

    float z[4];
#pragma unroll
    for (int j = 0; j < 4; j++) z[j] = y[j] * r2 * wv[j];

    const float4 c4 = *(const float4*)(cosb + (size_t)(CTX + q) * HD + lane * 4);
    const float4 s4 = *(const float4*)(sinb + (size_t)(CTX + q) * HD + lane * 4);
    const float cf[4] = {c4.x, c4.y, c4.z, c4.w};
    const float sf[4] = {s4.x, s4.y, s4.z, s4.w};

    float o_[4];
#pragma unroll
    for (int j = 0; j < 4; j++) {
        float p   = __shfl_xor_sync(0xffffffffu, z[j], 16);
        float rot = (lane < 16) ? -p : p;
        o_[j] = (z[j] * cf[j] + rot * sf[j]) * INV_SQRT_D;
    }
    half* dst = g_q_h + (size_t)((b * NH + h) * QL + q) * HD + lane * 4;
    *(uint2*)dst = make_uint2(pack2(o_[0], o_[1]), pack2(o_[2], o_[3]));
}

// ---------------------------------------------------------------------------
// KV-split flash attention (R9-best config). Grid (128 bh, 8 split),
// 256 threads, 2 CTAs/SM, 2-slot raw cp.async, half2 cs2 rope convert.
// ---------------------------------------------------------------------------
#define A_RAW_SLOT 32768
#define A_KH_BASE  (2 * A_RAW_SLOT)
#define A_VH_BASE  (A_KH_BASE + 17408)
#define A_MRED     (A_VH_BASE + 17408)
#define ASMEM_BYTES (A_MRED + 1024)

__global__ __launch_bounds__(256, 2) void attn_h(const float* __restrict__ th,
                                                 const float* __restrict__ hs)
{
    extern __shared__ char smc[];
    const uint32_t smBase = smaddr(smc);
    half*  Kh   = (half*)(smc + A_KH_BASE);
    half*  Vh   = (half*)(smc + A_VH_BASE);
    float* mred = (float*)(smc + A_MRED);
    float* lred = mred + 128;

    const int bh = blockIdx.x, h = bh & 31, b = bh >> 5;
    const int sp = blockIdx.y;
    const int c0 = (sp == 0) ? 0 : 9 + (sp - 1) * 8;
    const int c1 = (sp == 0) ? 9 : c0 + 8;

    const int tid = threadIdx.x, lane = tid & 31, wid = tid >> 5;
    const int gid = lane >> 2, tig = lane & 3;
    const int wq = wid >> 1, wg = wid & 1;
    const int r0 = wq * 16, j0 = wg * 32;

    const float* thb = th + (size_t)b * CTX * HID + h * HD;
    const float* hsb = hs + (size_t)b * QL  * HID + h * HD;

    auto load_chunk = [&](int c) {
        const uint32_t rS = smBase + (c & 1) * A_RAW_SLOT;
        const float* base = (c < 64) ? (thb + (size_t)c * 64 * HID) : hsb;
#pragma unroll
        for (int i = 0; i < 8; i++) {
            int u = tid + i * 256, j = u >> 5, d4 = u & 31;
            cpa16(rS + j * 512 + d4 * 16, base + (size_t)j * HID + d4 * 4);
        }
        CP_COMMIT();
    };

    load_chunk(c0); load_chunk(c0 + 1);

    // Q staging (fp16 source, via Kh temp) -> register fragments
    const half* qsrc = g_q_h + (size_t)bh * (QL * HD);
    for (int e = tid * 4; e < QL * HD; e += 1024) {
        int j = e >> 7, dd = e & 127;
        *(uint2*)&Kh[j * 136 + dd] = *(const uint2*)(qsrc + e);
    }
    __syncthreads();
    uint32_t qa[8][4];
    {
        const uint32_t qA = smBase + A_KH_BASE
                          + (uint32_t)((r0 + (lane & 15)) * 272 + (lane >> 4) * 16);
#pragma unroll
        for (int kd = 0; kd < 8; kd++)
            ldsm4(qa[kd][0], qa[kd][1], qa[kd][2], qa[kd][3], qA + kd * 32);
    }

    const uint32_t kA = smBase + A_KH_BASE
        + (uint32_t)((j0 + (lane & 7) + 8 * (lane >> 4)) * 272 + ((lane >> 3) & 1) * 16);
    const uint32_t vA = smBase + A_VH_BASE
        + (uint32_t)((j0 + (lane & 7) + 8 * ((lane >> 3) & 1)) * 272 + (lane >> 4) * 16);

    float m_lo = -1e30f, m_hi = -1e30f, l_lo = 0.f, l_hi = 0.f;
    float oacc[16][4];
#pragma unroll
    for (int nt = 0; nt < 16; nt++)
#pragma unroll
        for (int i = 0; i < 4; i++) oacc[nt][i] = 0.f;

    for (int t = c0; t < c1; t++) {
        CP_WAIT(1);
        __syncthreads();

        // half2 rope convert with sign-folded cs table
        {
            const float* rw = (const float*)(smc + (t & 1) * A_RAW_SLOT);
            const int p0 = t * 64;
#pragma unroll
            for (int e = tid * 4; e < 64 * 64; e += 1024) {
                int j = e >> 6, dl = e & 63;
                int p = p0 + j;
                int g = dl >> 2;
                float4 vlo = *(const float4*)&rw[j * 128 + dl];
                float4 vhi = *(const float4*)&rw[j * 128 + dl + 64];
                uint32_t vl0 = pack2(vlo.x, vlo.y), vl1 = pack2(vlo.z, vlo.w);
                uint32_t vh0 = pack2(vhi.x, vhi.y), vh1 = pack2(vhi.z, vhi.w);
                *(uint2*)&Vh[j * 136 + dl]      = make_uint2(vl0, vl1);
                *(uint2*)&Vh[j * 136 + dl + 64] = make_uint2(vh0, vh1);
                uint4 L = g_cs2[p * 32 + g];
                uint4 H = g_cs2[p * 32 + 16 + g];
                uint32_t klo0 = hfma2u(vl0, L.x, hmul2u(vh0, L.z));
                uint32_t klo1 = hfma2u(vl1, L.y, hmul2u(vh1, L.w));
                uint32_t khi0 = hfma2u(vh0, H.x, hmul2u(vl0, H.z));
                uint32_t khi1 = hfma2u(vh1, H.y, hmul2u(vl1, H.w));
                *(uint2*)&Kh[j * 136 + dl]      = make_uint2(klo0, klo1);
                *(uint2*)&Kh[j * 136 + dl + 64] = make_uint2(khi0, khi1);
            }
        }
        __syncthreads();
        if (t + 2 < c1) load_chunk(t + 2); else CP_COMMIT();

        // QK^T
        float sacc[4][4];
#pragma unroll
        for (int nt = 0; nt < 4; nt++)
#pragma unroll
            for (int i = 0; i < 4; i++) sacc[nt][i] = 0.f;
#pragma unroll
        for (int kd = 0; kd < 8; kd++) {
#pragma unroll
            for (int jt = 0; jt < 2; jt++) {
                uint32_t b0, b1, b2, b3;
                ldsm4(b0, b1, b2, b3, kA + jt * 16 * 272 + kd * 32);
                mma16816(sacc[jt * 2],     qa[kd][0], qa[kd][1], qa[kd][2], qa[kd][3], b0, b1);
                mma16816(sacc[jt * 2 + 1], qa[kd][0], qa[kd][1], qa[kd][2], qa[kd][3], b2, b3);
            }
        }

        // online softmax
        float mx_lo = -1e30f, mx_hi = -1e30f;
#pragma unroll
        for (int nt = 0; nt < 4; nt++) {
            mx_lo = fmaxf(mx_lo, fmaxf(sacc[nt][0], sacc[nt][1]));
            mx_hi = fmaxf(mx_hi, fmaxf(sacc[nt][2], sacc[nt][3]));
        }
        mx_lo = fmaxf(mx_lo, __shfl_xor_sync(0xffffffffu, mx_lo, 1));
        mx_lo = fmaxf(mx_lo, __shfl_xor_sync(0xffffffffu, mx_lo, 2));
        mx_hi = fmaxf(mx_hi, __shfl_xor_sync(0xffffffffu, mx_hi, 1));
        mx_hi = fmaxf(mx_hi, __shfl_xor_sync(0xffffffffu, mx_hi, 2));

        float nm_lo = fmaxf(m_lo, mx_lo), nm_hi = fmaxf(m_hi, mx_hi);
        float al_lo = __expf(m_lo - nm_lo), al_hi = __expf(m_hi - nm_hi);
        float sum_lo = 0.f, sum_hi = 0.f;
        uint32_t pa0[4], pa1[4];
#pragma unroll
        for (int nt = 0; nt < 4; nt++) {
            float e0 = __expf(sacc[nt][0] - nm_lo);
            float e1 = __expf(sacc[nt][1] - nm_lo);
            float e2 = __expf(sacc[nt][2] - nm_hi);
            float e3 = __expf(sacc[nt][3] - nm_hi);
            sum_lo += e0 + e1;  sum_hi += e2 + e3;
            pa0[nt] = pack2(e0, e1);
            pa1[nt] = pack2(e2, e3);
        }
        sum_lo += __shfl_xor_sync(0xffffffffu, sum_lo, 1);
        sum_lo += __shfl_xor_sync(0xffffffffu, sum_lo, 2);
        sum_hi += __shfl_xor_sync(0xffffffffu, sum_hi, 1);
        sum_hi += __shfl_xor_sync(0xffffffffu, sum_hi, 2);
        l_lo = l_lo * al_lo + sum_lo;  l_hi = l_hi * al_hi + sum_hi;
        m_lo = nm_lo;  m_hi = nm_hi;

#pragma unroll
        for (int nt = 0; nt < 16; nt++) {
            oacc[nt][0] *= al_lo; oacc[nt][1] *= al_lo;
            oacc[nt][2] *= al_hi; oacc[nt][3] *= al_hi;
        }

        // PV
#pragma unroll
        for (int kc = 0; kc < 2; kc++) {
            uint32_t a0 = pa0[2 * kc], a1 = pa1[2 * kc];
            uint32_t a2 = pa0[2 * kc + 1], a3 = pa1[2 * kc + 1];
#pragma unroll
            for (int dt = 0; dt < 8; dt++) {
                uint32_t b0, b1, b2, b3;
                ldsm4t(b0, b1, b2, b3, vA + kc * 16 * 272 + dt * 32);
                mma16816(oacc[dt * 2],     a0, a1, a2, a3, b0, b1);
                mma16816(oacc[dt * 2 + 1], a0, a1, a2, a3, b2, b3);
            }
        }
    }

    CP_WAIT(0);
    // in-CTA merge of the 2 key stripes -> partial (unnormalized O, m, l)
    const int rlo = r0 + gid, rhi = r0 + gid + 8;
    if (tig == 0) {
        mred[wg * 64 + rlo] = m_lo;  mred[wg * 64 + rhi] = m_hi;
        lred[wg * 64 + rlo] = l_lo;  lred[wg * 64 + rhi] = l_hi;
    }
    __syncthreads();
    float M_lo = fmaxf(mred[rlo], mred[64 + rlo]);
    float M_hi = fmaxf(mred[rhi], mred[64 + rhi]);
    float L_lo = lred[rlo] * __expf(mred[rlo] - M_lo)
               + lred[64 + rlo] * __expf(mred[64 + rlo] - M_lo);
    float L_hi = lred[rhi] * __expf(mred[rhi] - M_hi)
               + lred[64 + rhi] * __expf(mred[64 + rhi] - M_hi);
    float sc_lo = __expf(m_lo - M_lo);
    float sc_hi = __expf(m_hi - M_hi);
#pragma unroll
    for (int nt = 0; nt < 16; nt++) {
        oacc[nt][0] *= sc_lo; oacc[nt][1] *= sc_lo;
        oacc[nt][2] *= sc_hi; oacc[nt][3] *= sc_hi;
    }

    const size_t pbase = ((size_t)sp * NB * NH + bh) * QL;
    if (tig == 0 && wg == 0) {
        g_pm[pbase + rlo] = M_lo;  g_pm[pbase + rhi] = M_hi;
        g_pl[pbase + rlo] = L_lo;  g_pl[pbase + rhi] = L_hi;
    }

    float* OsmF = (float*)smc;
    if (wg == 0) {
#pragma unroll
        for (int nt = 0; nt < 16; nt++) {
            const int col = nt * 8 + 2 * tig;
            *(float2*)&OsmF[rlo * 128 + col] = make_float2(oacc[nt][0], oacc[nt][1]);
            *(float2*)&OsmF[rhi * 128 + col] = make_float2(oacc[nt][2], oacc[nt][3]);
        }
    }
    __syncthreads();
    if (wg == 1) {
#pragma unroll
        for (int nt = 0; nt < 16; nt++) {
            const int col = nt * 8 + 2 * tig;
            float2 v0 = *(float2*)&OsmF[rlo * 128 + col];
            float2 v1 = *(float2*)&OsmF[rhi * 128 + col];
            *(float2*)&OsmF[rlo * 128 + col] = make_float2(oacc[nt][0] + v0.x, oacc[nt][1] + v0.y);
            *(float2*)&OsmF[rhi * 128 + col] = make_float2(oacc[nt][2] + v1.x, oacc[nt][3] + v1.y);
        }
    }
    __syncthreads();

    float* pO = g_pO + pbase * HD;
    for (int e = tid * 4; e < QL * HD; e += 1024)
        *(float4*)(pO + e) = *(const float4*)&OsmF[e];
}

// ---------------------------------------------------------------------------
// merge the splits -> fp16 attention output
// ---------------------------------------------------------------------------
__global__ __launch_bounds__(256) void merge_k()
{
    __shared__ float sc[SPLIT][64];
    const int bh = blockIdx.x, h = bh & 31, b = bh >> 5;
    const int tid = threadIdx.x;

    if (tid < 64) {
        float m[SPLIT], l[SPLIT];
#pragma unroll
        for (int s = 0; s < SPLIT; s++) {
            size_t pb = ((size_t)s * NB * NH + bh) * QL + tid;
            m[s] = g_pm[pb];  l[s] = g_pl[pb];
        }
        float M = m[0];
#pragma unroll
        for (int s = 1; s < SPLIT; s++) M = fmaxf(M, m[s]);
        float L = 0.f;
#pragma unroll
        for (int s = 0; s < SPLIT; s++) L += l[s] * __expf(m[s] - M);
        float invL = 1.f / L;
#pragma unroll
        for (int s = 0; s < SPLIT; s++) sc[s][tid] = __expf(m[s] - M) * invL;
    }
    __syncthreads();

    for (int e = tid * 4; e < QL * HD; e += 1024) {
        int row = e >> 7, dd = e & 127;
        float4 acc = make_float4(0.f, 0.f, 0.f, 0.f);
#pragma unroll
        for (int s = 0; s < SPLIT; s++) {
            const float* pO = g_pO + (((size_t)s * NB * NH + bh) * QL) * HD + e;
            float4 v = *(const float4*)pO;
            float f = sc[s][row];
            acc.x += f * v.x; acc.y += f * v.y; acc.z += f * v.z; acc.w += f * v.w;
        }
        *(uint2*)(g_attn_h + (size_t)(b * QL + row) * HID + h * HD + dd) =
            make_uint2(pack2(acc.x, acc.y), pack2(acc.z, acc.w));
    }
}

// ---------------------------------------------------------------------------
extern "C" void kernel_launch(void* const* d_in, const int* in_sizes, int n_in,
                              void* d_out, int out_size)
{
    const float* hs   = (const float*)d_in[0];
    const float* th   = (const float*)d_in[1];
    const float* cosb = (const float*)d_in[2];
    const float* sinb = (const float*)d_in[3];
    const float* Wqkv = (const float*)d_in[4];
    const float* Wo   = (const float*)d_in[5];
    const float* qw   = (const float*)d_in[6];
    float* out = (float*)d_out;

    float *qraw_p;
    half *hs_h, *attn_h_p;
    cudaGetSymbolAddress((void**)&qraw_p, g_qraw);
    cudaGetSymbolAddress((void**)&hs_h,   g_hs_h);
    cudaGetSymbolAddress((void**)&attn_h_p, g_attn_h);

    cudaFuncSetAttribute(hgemm4, cudaFuncAttributeMaxDynamicSharedMemorySize, G4_SMEM);
    cudaFuncSetAttribute(attn_h, cudaFuncAttributeMaxDynamicSharedMemorySize, ASMEM_BYTES);

    static cudaStream_t s1 = nullptr;
    static cudaEvent_t evRoot = nullptr, evCS = nullptr;
    if (!s1) {
        cudaStreamCreateWithFlags(&s1, cudaStreamNonBlocking);
        cudaEventCreateWithFlags(&evRoot, cudaEventDisableTiming);
        cudaEventCreateWithFlags(&evCS,   cudaEventDisableTiming);
    }

    cudaEventRecord(evRoot, 0);

    // side stream: cs table only (needed by attn)
    cudaStreamWaitEvent(s1, evRoot, 0);
    cs2_prep<<<(TOT * 32 + 255) / 256, 256, 0, s1>>>(cosb, sinb);
    cudaEventRecord(evCS, s1);

    dim3 gg(64, 8);
    // main critical path (fused weight conversion inside the GEMMs)
    cvt_f2h<<<256,  256>>>(hs, hs_h, HID);                            // #1
    hgemm4<<<gg, 128, G4_SMEM>>>(hs_h, Wqkv, 3 * HID, qraw_p);        // #2
    qnorm_rope_k<<<1024, 256>>>(cosb, sinb, qw);                      // #3

    cudaStreamWaitEvent((cudaStream_t)0, evCS, 0);
    attn_h<<<dim3(NB * NH, SPLIT), 256, ASMEM_BYTES>>>(th, hs);       // #4 (profiled)
    merge_k<<<NB * NH, 256>>>();                                      // #5
    hgemm4<<<gg, 128, G4_SMEM>>>(attn_h_p, Wo, HID, out);             // #6
}

// round 17
// speedup vs baseline: 1.1893x; 1.1478x over previous
#include <cuda_runtime.h>
#include <cuda_fp16.h>
#include <math.h>
#include <stdint.h>

#define NB    4
#define QL    64
#define NH    32
#define HD    128
#define CTX   4096
#define TOT   4160
#define HID   4096
#define EPSR  1e-6f
#define INV_SQRT_D 0.08838834764831843f
#define SPLIT 8

__device__ float g_qraw[NB * QL * HID];
__device__ half  g_q_h [NB * NH * QL * HD];
__device__ half  g_hs_h [NB * QL * HID];
__device__ half  g_attn_h[NB * QL * HID];
__device__ half  g_wq_h[HID * HID];
__device__ half  g_wo_h[HID * HID];
__device__ uint4 g_cs2[TOT * 32];
__device__ float g_pO[SPLIT * NB * NH * QL * HD];
__device__ float g_pm[SPLIT * NB * NH * QL];
__device__ float g_pl[SPLIT * NB * NH * QL];

// ---------------------------------------------------------------------------
// helpers
// ---------------------------------------------------------------------------
__device__ __forceinline__ uint32_t smaddr(const void* p) {
    return (uint32_t)__cvta_generic_to_shared(p);
}
__device__ __forceinline__ void ldsm4(uint32_t& r0, uint32_t& r1, uint32_t& r2, uint32_t& r3, uint32_t a) {
    asm volatile("ldmatrix.sync.aligned.m8n8.x4.shared.b16 {%0,%1,%2,%3}, [%4];"
                 : "=r"(r0), "=r"(r1), "=r"(r2), "=r"(r3) : "r"(a));
}
__device__ __forceinline__ void ldsm4t(uint32_t& r0, uint32_t& r1, uint32_t& r2, uint32_t& r3, uint32_t a) {
    asm volatile("ldmatrix.sync.aligned.m8n8.x4.trans.shared.b16 {%0,%1,%2,%3}, [%4];"
                 : "=r"(r0), "=r"(r1), "=r"(r2), "=r"(r3) : "r"(a));
}
__device__ __forceinline__ void mma16816(float d[4],
                                         uint32_t a0, uint32_t a1, uint32_t a2, uint32_t a3,
                                         uint32_t b0, uint32_t b1) {
    asm volatile(
        "mma.sync.aligned.m16n8k16.row.col.f32.f16.f16.f32 "
        "{%0,%1,%2,%3},{%4,%5,%6,%7},{%8,%9},{%0,%1,%2,%3};"
        : "+f"(d[0]), "+f"(d[1]), "+f"(d[2]), "+f"(d[3])
        : "r"(a0), "r"(a1), "r"(a2), "r"(a3), "r"(b0), "r"(b1));
}
__device__ __forceinline__ uint32_t pack2(float x, float y) {
    __half2 h = __floats2half2_rn(x, y);
    return *(uint32_t*)&h;
}
__device__ __forceinline__ uint32_t hfma2u(uint32_t a, uint32_t b, uint32_t c) {
    __half2 r = __hfma2(*(__half2*)&a, *(__half2*)&b, *(__half2*)&c);
    return *(uint32_t*)&r;
}
__device__ __forceinline__ uint32_t hmul2u(uint32_t a, uint32_t b) {
    __half2 r = __hmul2(*(__half2*)&a, *(__half2*)&b);
    return *(uint32_t*)&r;
}
__device__ __forceinline__ void cpa16(uint32_t dst, const void* src) {
    asm volatile("cp.async.cg.shared.global [%0], [%1], 16;" :: "r"(dst), "l"(src));
}
#define CP_COMMIT() asm volatile("cp.async.commit_group;")
#define CP_WAIT(n)  asm volatile("cp.async.wait_group %0;" :: "n"(n))

// ---------------------------------------------------------------------------
// fp32 -> fp16 conversion, 16 elems/thread. cols fixed at 4096.
// ---------------------------------------------------------------------------
__global__ __launch_bounds__(256) void cvt_f2h(const float* __restrict__ src,
                                               half* __restrict__ dst, int ld)
{
    size_t i = ((size_t)blockIdx.x * 256 + threadIdx.x) * 16;
    size_t row = i >> 12;
    int    col = (int)(i & 4095);
    const float* s = src + row * (size_t)ld + col;
    half* d = dst + row * 4096 + col;
    float4 v0 = *(const float4*)(s);
    float4 v1 = *(const float4*)(s + 4);
    float4 v2 = *(const float4*)(s + 8);
    float4 v3 = *(const float4*)(s + 12);
    *(uint2*)(d)      = make_uint2(pack2(v0.x, v0.y), pack2(v0.z, v0.w));
    *(uint2*)(d + 4)  = make_uint2(pack2(v1.x, v1.y), pack2(v1.z, v1.w));
    *(uint2*)(d + 8)  = make_uint2(pack2(v2.x, v2.y), pack2(v2.z, v2.w));
    *(uint2*)(d + 12) = make_uint2(pack2(v3.x, v3.y), pack2(v3.z, v3.w));
}

// sign-folded packed (c, +/-s) table
__global__ __launch_bounds__(256) void cs2_prep(const float* __restrict__ cosb,
                                                const float* __restrict__ sinb)
{
    int i = blockIdx.x * 256 + threadIdx.x;
    if (i >= TOT * 32) return;
    int g    = i & 15;
    int half_ = (i >> 4) & 1;
    int p    = i >> 5;
    int d0   = half_ * 64 + g * 4;
    float4 c = *(const float4*)(cosb + (size_t)p * HD + d0);
    float4 s = *(const float4*)(sinb + (size_t)p * HD + d0);
    float sgn = half_ ? 1.f : -1.f;
    uint4 out;
    out.x = pack2(c.x, c.y);
    out.y = pack2(c.z, c.w);
    out.z = pack2(sgn * s.x, sgn * s.y);
    out.w = pack2(sgn * s.z, sgn * s.w);
    g_cs2[i] = out;
}

// ---------------------------------------------------------------------------
// fp16 GEMM, BM=32 BN=64 BK=64, 128 threads, 4-stage cp.async, 4 CTAs/SM.
// ---------------------------------------------------------------------------
#define G3_ASLOT 4608
#define G3_BSLOT 9216
#define G3_STAGE (G3_ASLOT + G3_BSLOT)
#define G3_SMEM  (4 * G3_STAGE)

__global__ __launch_bounds__(128, 4) void hgemm3(const half* __restrict__ A,
                                                 const half* __restrict__ B,
                                                 float* __restrict__ C)
{
    extern __shared__ char smc[];
    const uint32_t smBase = smaddr(smc);
    const int tid = threadIdx.x, lane = tid & 31, wid = tid >> 5;
    const int gid = lane >> 2, tig = lane & 3;
    const int wm = wid >> 1, wn = wid & 1;
    const int bx = blockIdx.x, by = blockIdx.y;

    const half* Ab = A + (size_t)(by * 32) * HID;
    const half* Bb = B + (size_t)(bx * 64);

    float acc[4][4];
#pragma unroll
    for (int nt = 0; nt < 4; nt++)
#pragma unroll
        for (int i = 0; i < 4; i++) acc[nt][i] = 0.f;

    const uint32_t aOff = (uint32_t)((wm * 16 + (lane & 15)) * 144 + (lane >> 4) * 16);
    const uint32_t bOff = (uint32_t)(((lane & 7) + 8 * ((lane >> 3) & 1)) * 144
                                     + (wn * 32 + 8 * (lane >> 4)) * 2);

    auto load_stage = [&](int kt) {
        const int slot = kt & 3;
        const int k0 = kt * 64;
        const uint32_t aS = smBase + slot * G3_STAGE;
        const uint32_t bS = aS + G3_ASLOT;
#pragma unroll
        for (int i = 0; i < 2; i++) {
            int u = tid + i * 128, r = u >> 3, c = u & 7;
            cpa16(aS + r * 144 + c * 16, Ab + (size_t)r * HID + k0 + c * 8);
        }
#pragma unroll
        for (int i = 0; i < 4; i++) {
            int u = tid + i * 128, r = u >> 3, c = u & 7;
            cpa16(bS + r * 144 + c * 16, Bb + (size_t)(k0 + r) * HID + c * 8);
        }
        CP_COMMIT();
    };

    load_stage(0); load_stage(1); load_stage(2);

    const int NK = HID / 64;
    for (int kt = 0; kt < NK; kt++) {
        CP_WAIT(2);
        __syncthreads();
        if (kt + 3 < NK) load_stage(kt + 3); else CP_COMMIT();

        const uint32_t aA = smBase + (kt & 3) * G3_STAGE + aOff;
        const uint32_t bA = smBase + (kt & 3) * G3_STAGE + G3_ASLOT + bOff;
#pragma unroll
        for (int kk = 0; kk < 4; kk++) {
            uint32_t x0, x1, x2, x3;
            ldsm4(x0, x1, x2, x3, aA + kk * 32);
#pragma unroll
            for (int nt2 = 0; nt2 < 2; nt2++) {
                uint32_t b0, b1, b2, b3;
                ldsm4t(b0, b1, b2, b3, bA + kk * 16 * 144 + nt2 * 32);
                mma16816(acc[nt2 * 2],     x0, x1, x2, x3, b0, b1);
                mma16816(acc[nt2 * 2 + 1], x0, x1, x2, x3, b2, b3);
            }
        }
    }

    const int row = by * 32 + wm * 16 + gid;
#pragma unroll
    for (int nt = 0; nt < 4; nt++) {
        const int col = bx * 64 + wn * 32 + nt * 8 + 2 * tig;
        *(float2*)(C + (size_t)row * HID + col) =
            make_float2(acc[nt][0], acc[nt][1]);
        *(float2*)(C + (size_t)(row + 8) * HID + col) =
            make_float2(acc[nt][2], acc[nt][3]);
    }
}

// ---------------------------------------------------------------------------
// Q: double RMSNorm + RoPE + fold 1/sqrt(D); writes fp16 directly.
// ---------------------------------------------------------------------------
__global__ __launch_bounds__(256) void qnorm_rope_k(const float* __restrict__ cosb,
                                                    const float* __restrict__ sinb,
                                                    const float* __restrict__ w)
{
    const int gw   = (blockIdx.x * 256 + threadIdx.x) >> 5;
    const int lane = threadIdx.x & 31;
    const int h = gw & 31;
    const int q = (gw >> 5) & 63;
    const int b = gw >> 11;

    const float* src = g_qraw + (size_t)(b * QL + q) * HID + h * HD + lane * 4;
    float4 x4 = *(const float4*)src;
    float  x[4] = {x4.x, x4.y, x4.z, x4.w};
    float4 w4 = *(const float4*)(w + lane * 4);
    float  wv[4] = {w4.x, w4.y, w4.z, w4.w};

    float ss = x[0]*x[0] + x[1]*x[1] + x[2]*x[2] + x[3]*x[3];
#pragma unroll
    for (int o = 16; o > 0; o >>= 1) ss += __shfl_xor_sync(0xffffffffu, ss, o);
    float r1 = rsqrtf(ss * (1.f / 128.f) + EPSR);

    float y[4];
#pragma unroll
    for (int j = 0; j < 4; j++) y[j] = x[j] * r1 * wv[j];

    float ss2 = y[0]*y[0] + y[1]*y[1] + y[2]*y[2] + y[3]*y[3];
#pragma unroll
    for (int o = 16; o > 0; o >>= 1) ss2 += __shfl_xor_sync(0xffffffffu, ss2, o);
    float r2 = rsqrtf(ss2 * (1.f / 128.f) + EPSR);

    float z[4];
#pragma unroll
    for (int j = 0; j < 4; j++) z[j] = y[j] * r2 * wv[j];

    const float4 c4 = *(const float4*)(cosb + (size_t)(CTX + q) * HD + lane * 4);
    const float4 s4 = *(const float4*)(sinb + (size_t)(CTX + q) * HD + lane * 4);
    const float cf[4] = {c4.x, c4.y, c4.z, c4.w};
    const float sf[4] = {s4.x, s4.y, s4.z, s4.w};

    float o_[4];
#pragma unroll
    for (int j = 0; j < 4; j++) {
        float p   = __shfl_xor_sync(0xffffffffu, z[j], 16);
        float rot = (lane < 16) ? -p : p;
        o_[j] = (z[j] * cf[j] + rot * sf[j]) * INV_SQRT_D;
    }
    half* dst = g_q_h + (size_t)((b * NH + h) * QL + q) * HD + lane * 4;
    *(uint2*)dst = make_uint2(pack2(o_[0], o_[1]), pack2(o_[2], o_[3]));
}

// ---------------------------------------------------------------------------
// KV-split flash attention, 4 CTAs/SM version.
// 128 threads = 4 warps = 4 q-tiles x ONE 32-key stripe; chunk = 32 keys
// (130 chunks, no tail). 2-slot raw cp.async + half2 cs2 rope convert.
// No cross-warp merge needed: each warp owns full rows.
// smem: raw 2x16KB + Kh/Vh 2x8.7KB = 50.2KB -> 4 CTAs/SM.
// ---------------------------------------------------------------------------
#define A2_RAW_SLOT 16384                    // 32*128*4
#define A2_KH       (2 * A2_RAW_SLOT)        // 32768
#define A2_VH       (A2_KH + 8704)           // 41472
#define ASMEM_BYTES (A2_VH + 8704)           // 50176

__global__ __launch_bounds__(128, 4) void attn_h(const float* __restrict__ th,
                                                 const float* __restrict__ hs)
{
    extern __shared__ char smc[];
    const uint32_t smBase = smaddr(smc);
    half* Kh = (half*)(smc + A2_KH);
    half* Vh = (half*)(smc + A2_VH);

    const int bh = blockIdx.x, h = bh & 31, b = bh >> 5;
    const int sp = blockIdx.y;
    const int c0 = (sp < 2) ? sp * 17 : 34 + (sp - 2) * 16;
    const int c1 = c0 + ((sp < 2) ? 17 : 16);

    const int tid = threadIdx.x, lane = tid & 31, wid = tid >> 5;
    const int gid = lane >> 2, tig = lane & 3;
    const int r0 = wid * 16;

    const float* thb = th + (size_t)b * CTX * HID + h * HD;
    const float* hsb = hs + (size_t)b * QL  * HID + h * HD;

    auto load_chunk = [&](int c) {
        const uint32_t rS = smBase + (c & 1) * A2_RAW_SLOT;
        const float* base = (c < 128) ? (thb + (size_t)c * 32 * HID)
                                      : (hsb + (size_t)(c - 128) * 32 * HID);
#pragma unroll
        for (int i = 0; i < 8; i++) {
            int u = tid + i * 128, j = u >> 5, d4 = u & 31;
            cpa16(rS + j * 512 + d4 * 16, base + (size_t)j * HID + d4 * 4);
        }
        CP_COMMIT();
    };

    load_chunk(c0); load_chunk(c0 + 1);

    // Q staging (64 rows x 272B spans Kh+Vh exactly) -> register fragments
    {
        half* Qtmp = Kh;
        const half* qsrc = g_q_h + (size_t)bh * (QL * HD);
        for (int e = tid * 4; e < QL * HD; e += 512) {
            int j = e >> 7, dd = e & 127;
            *(uint2*)&Qtmp[j * 136 + dd] = *(const uint2*)(qsrc + e);
        }
    }
    __syncthreads();
    uint32_t qa[8][4];
    {
        const uint32_t qA = smBase + A2_KH
                          + (uint32_t)((r0 + (lane & 15)) * 272 + (lane >> 4) * 16);
#pragma unroll
        for (int kd = 0; kd < 8; kd++)
            ldsm4(qa[kd][0], qa[kd][1], qa[kd][2], qa[kd][3], qA + kd * 32);
    }
    __syncthreads();   // Kh/Vh now free for KV

    const uint32_t kA = smBase + A2_KH
        + (uint32_t)(((lane & 7) + 8 * (lane >> 4)) * 272 + ((lane >> 3) & 1) * 16);
    const uint32_t vA = smBase + A2_VH
        + (uint32_t)(((lane & 7) + 8 * ((lane >> 3) & 1)) * 272 + (lane >> 4) * 16);

    float m_lo = -1e30f, m_hi = -1e30f, l_lo = 0.f, l_hi = 0.f;
    float oacc[16][4];
#pragma unroll
    for (int nt = 0; nt < 16; nt++)
#pragma unroll
        for (int i = 0; i < 4; i++) oacc[nt][i] = 0.f;

    for (int t = c0; t < c1; t++) {
        CP_WAIT(1);
        __syncthreads();

        // half2 rope convert with sign-folded cs table (32 keys)
        {
            const float* rw = (const float*)(smc + (t & 1) * A2_RAW_SLOT);
            const int p0 = t * 32;
#pragma unroll
            for (int e = tid * 4; e < 32 * 64; e += 512) {
                int j = e >> 6, dl = e & 63;
                int p = p0 + j;
                int g = dl >> 2;
                float4 vlo = *(const float4*)&rw[j * 128 + dl];
                float4 vhi = *(const float4*)&rw[j * 128 + dl + 64];
                uint32_t vl0 = pack2(vlo.x, vlo.y), vl1 = pack2(vlo.z, vlo.w);
                uint32_t vh0 = pack2(vhi.x, vhi.y), vh1 = pack2(vhi.z, vhi.w);
                *(uint2*)&Vh[j * 136 + dl]      = make_uint2(vl0, vl1);
                *(uint2*)&Vh[j * 136 + dl + 64] = make_uint2(vh0, vh1);
                uint4 L = g_cs2[p * 32 + g];
                uint4 H = g_cs2[p * 32 + 16 + g];
                uint32_t klo0 = hfma2u(vl0, L.x, hmul2u(vh0, L.z));
                uint32_t klo1 = hfma2u(vl1, L.y, hmul2u(vh1, L.w));
                uint32_t khi0 = hfma2u(vh0, H.x, hmul2u(vl0, H.z));
                uint32_t khi1 = hfma2u(vh1, H.y, hmul2u(vl1, H.w));
                *(uint2*)&Kh[j * 136 + dl]      = make_uint2(klo0, klo1);
                *(uint2*)&Kh[j * 136 + dl + 64] = make_uint2(khi0, khi1);
            }
        }
        __syncthreads();
        if (t + 2 < c1) load_chunk(t + 2); else CP_COMMIT();

        // QK^T: S[16q][32k] per warp
        float sacc[4][4];
#pragma unroll
        for (int nt = 0; nt < 4; nt++)
#pragma unroll
            for (int i = 0; i < 4; i++) sacc[nt][i] = 0.f;
#pragma unroll
        for (int kd = 0; kd < 8; kd++) {
#pragma unroll
            for (int jt = 0; jt < 2; jt++) {
                uint32_t b0, b1, b2, b3;
                ldsm4(b0, b1, b2, b3, kA + jt * 16 * 272 + kd * 32);
                mma16816(sacc[jt * 2],     qa[kd][0], qa[kd][1], qa[kd][2], qa[kd][3], b0, b1);
                mma16816(sacc[jt * 2 + 1], qa[kd][0], qa[kd][1], qa[kd][2], qa[kd][3], b2, b3);
            }
        }

        // online softmax (rows r0+gid, r0+gid+8)
        float mx_lo = -1e30f, mx_hi = -1e30f;
#pragma unroll
        for (int nt = 0; nt < 4; nt++) {
            mx_lo = fmaxf(mx_lo, fmaxf(sacc[nt][0], sacc[nt][1]));
            mx_hi = fmaxf(mx_hi, fmaxf(sacc[nt][2], sacc[nt][3]));
        }
        mx_lo = fmaxf(mx_lo, __shfl_xor_sync(0xffffffffu, mx_lo, 1));
        mx_lo = fmaxf(mx_lo, __shfl_xor_sync(0xffffffffu, mx_lo, 2));
        mx_hi = fmaxf(mx_hi, __shfl_xor_sync(0xffffffffu, mx_hi, 1));
        mx_hi = fmaxf(mx_hi, __shfl_xor_sync(0xffffffffu, mx_hi, 2));

        float nm_lo = fmaxf(m_lo, mx_lo), nm_hi = fmaxf(m_hi, mx_hi);
        float al_lo = __expf(m_lo - nm_lo), al_hi = __expf(m_hi - nm_hi);
        float sum_lo = 0.f, sum_hi = 0.f;
        uint32_t pa0[4], pa1[4];
#pragma unroll
        for (int nt = 0; nt < 4; nt++) {
            float e0 = __expf(sacc[nt][0] - nm_lo);
            float e1 = __expf(sacc[nt][1] - nm_lo);
            float e2 = __expf(sacc[nt][2] - nm_hi);
            float e3 = __expf(sacc[nt][3] - nm_hi);
            sum_lo += e0 + e1;  sum_hi += e2 + e3;
            pa0[nt] = pack2(e0, e1);
            pa1[nt] = pack2(e2, e3);
        }
        sum_lo += __shfl_xor_sync(0xffffffffu, sum_lo, 1);
        sum_lo += __shfl_xor_sync(0xffffffffu, sum_lo, 2);
        sum_hi += __shfl_xor_sync(0xffffffffu, sum_hi, 1);
        sum_hi += __shfl_xor_sync(0xffffffffu, sum_hi, 2);
        l_lo = l_lo * al_lo + sum_lo;  l_hi = l_hi * al_hi + sum_hi;
        m_lo = nm_lo;  m_hi = nm_hi;

#pragma unroll
        for (int nt = 0; nt < 16; nt++) {
            oacc[nt][0] *= al_lo; oacc[nt][1] *= al_lo;
            oacc[nt][2] *= al_hi; oacc[nt][3] *= al_hi;
        }

        // PV: O[16q][128d] += P[16][32] @ V[32][128]
#pragma unroll
        for (int kc = 0; kc < 2; kc++) {
            uint32_t a0 = pa0[2 * kc], a1 = pa1[2 * kc];
            uint32_t a2 = pa0[2 * kc + 1], a3 = pa1[2 * kc + 1];
#pragma unroll
            for (int dt = 0; dt < 8; dt++) {
                uint32_t b0, b1, b2, b3;
                ldsm4t(b0, b1, b2, b3, vA + kc * 16 * 272 + dt * 32);
                mma16816(oacc[dt * 2],     a0, a1, a2, a3, b0, b1);
                mma16816(oacc[dt * 2 + 1], a0, a1, a2, a3, b2, b3);
            }
        }
        __syncthreads();   // all warps done with Kh/Vh before next convert
    }

    CP_WAIT(0);
    // epilogue: single stripe owns full rows -> write (m, l, unnormalized O)
    const int rlo = r0 + gid, rhi = r0 + gid + 8;
    const size_t pbase = ((size_t)sp * NB * NH + bh) * QL;
    if (tig == 0) {
        g_pm[pbase + rlo] = m_lo;  g_pm[pbase + rhi] = m_hi;
        g_pl[pbase + rlo] = l_lo;  g_pl[pbase + rhi] = l_hi;
    }
    float* pO = g_pO + pbase * HD;
#pragma unroll
    for (int nt = 0; nt < 16; nt++) {
        const int col = nt * 8 + 2 * tig;
        *(float2*)(pO + (size_t)rlo * HD + col) = make_float2(oacc[nt][0], oacc[nt][1]);
        *(float2*)(pO + (size_t)rhi * HD + col) = make_float2(oacc[nt][2], oacc[nt][3]);
    }
}

// ---------------------------------------------------------------------------
// merge the splits -> fp16 attention output
// ---------------------------------------------------------------------------
__global__ __launch_bounds__(256) void merge_k()
{
    __shared__ float sc[SPLIT][64];
    const int bh = blockIdx.x, h = bh & 31, b = bh >> 5;
    const int tid = threadIdx.x;

    if (tid < 64) {
        float m[SPLIT], l[SPLIT];
#pragma unroll
        for (int s = 0; s < SPLIT; s++) {
            size_t pb = ((size_t)s * NB * NH + bh) * QL + tid;
            m[s] = g_pm[pb];  l[s] = g_pl[pb];
        }
        float M = m[0];
#pragma unroll
        for (int s = 1; s < SPLIT; s++) M = fmaxf(M, m[s]);
        float L = 0.f;
#pragma unroll
        for (int s = 0; s < SPLIT; s++) L += l[s] * __expf(m[s] - M);
        float invL = 1.f / L;
#pragma unroll
        for (int s = 0; s < SPLIT; s++) sc[s][tid] = __expf(m[s] - M) * invL;
    }
    __syncthreads();

    for (int e = tid * 4; e < QL * HD; e += 1024) {
        int row = e >> 7, dd = e & 127;
        float4 acc = make_float4(0.f, 0.f, 0.f, 0.f);
#pragma unroll
        for (int s = 0; s < SPLIT; s++) {
            const float* pO = g_pO + (((size_t)s * NB * NH + bh) * QL) * HD + e;
            float4 v = *(const float4*)pO;
            float f = sc[s][row];
            acc.x += f * v.x; acc.y += f * v.y; acc.z += f * v.z; acc.w += f * v.w;
        }
        *(uint2*)(g_attn_h + (size_t)(b * QL + row) * HID + h * HD + dd) =
            make_uint2(pack2(acc.x, acc.y), pack2(acc.z, acc.w));
    }
}

// ---------------------------------------------------------------------------
extern "C" void kernel_launch(void* const* d_in, const int* in_sizes, int n_in,
                              void* d_out, int out_size)
{
    const float* hs   = (const float*)d_in[0];
    const float* th   = (const float*)d_in[1];
    const float* cosb = (const float*)d_in[2];
    const float* sinb = (const float*)d_in[3];
    const float* Wqkv = (const float*)d_in[4];
    const float* Wo   = (const float*)d_in[5];
    const float* qw   = (const float*)d_in[6];
    float* out = (float*)d_out;

    float *qraw_p;
    half *hs_h, *attn_h_p, *wq_h, *wo_h;
    cudaGetSymbolAddress((void**)&qraw_p, g_qraw);
    cudaGetSymbolAddress((void**)&hs_h,   g_hs_h);
    cudaGetSymbolAddress((void**)&attn_h_p, g_attn_h);
    cudaGetSymbolAddress((void**)&wq_h,   g_wq_h);
    cudaGetSymbolAddress((void**)&wo_h,   g_wo_h);

    cudaFuncSetAttribute(hgemm3, cudaFuncAttributeMaxDynamicSharedMemorySize, G3_SMEM);
    cudaFuncSetAttribute(attn_h, cudaFuncAttributeMaxDynamicSharedMemorySize, ASMEM_BYTES);

    static cudaStream_t s1 = nullptr;
    static cudaEvent_t evRoot = nullptr, evCS = nullptr, evWO = nullptr;
    if (!s1) {
        cudaStreamCreateWithFlags(&s1, cudaStreamNonBlocking);
        cudaEventCreateWithFlags(&evRoot, cudaEventDisableTiming);
        cudaEventCreateWithFlags(&evCS,   cudaEventDisableTiming);
        cudaEventCreateWithFlags(&evWO,   cudaEventDisableTiming);
    }

    cudaEventRecord(evRoot, 0);

    dim3 gg(64, 8);
    // main critical path
    cvt_f2h<<<256,  256>>>(hs,   hs_h, HID);                        // #1
    cvt_f2h<<<4096, 256>>>(Wqkv, wq_h, 3 * HID);                    // #2
    hgemm3<<<gg, 128, G3_SMEM>>>(hs_h, wq_h, qraw_p);               // #3
    qnorm_rope_k<<<1024, 256>>>(cosb, sinb, qw);                    // #4

    // side stream: cs table (needed by attn) + Wo convert (needed at end)
    cudaStreamWaitEvent(s1, evRoot, 0);
    cs2_prep<<<(TOT * 32 + 255) / 256, 256, 0, s1>>>(cosb, sinb);   // #5
    cudaEventRecord(evCS, s1);

    cudaStreamWaitEvent((cudaStream_t)0, evCS, 0);
    attn_h<<<dim3(NB * NH, SPLIT), 128, ASMEM_BYTES>>>(th, hs);     // #6 (profiled)
    merge_k<<<NB * NH, 256>>>();                                    // #7

    cvt_f2h<<<4096, 256, 0, s1>>>(Wo, wo_h, HID);                   // (side)
    cudaEventRecord(evWO, s1);
    cudaStreamWaitEvent((cudaStream_t)0, evWO, 0);
    hgemm3<<<gg, 128, G3_SMEM>>>(attn_h_p, wo_h, out);              // #8
}